// round 1
// baseline (speedup 1.0000x reference)
#include <cuda_runtime.h>

#define HIDDEN 1024
#define SEQ    2048
#define BATCH  2
#define MTOT   (BATCH * SEQ)   // 4096 rows

// Scratch (allocation-free rule: __device__ globals). 4 x 16MB.
__device__ float g_q  [(size_t)MTOT * HIDDEN];
__device__ float g_k  [(size_t)MTOT * HIDDEN];
__device__ float g_v  [(size_t)MTOT * HIDDEN];
__device__ float g_ctx[(size_t)MTOT * HIDDEN];

// ---------------------------------------------------------------------------
// C[m][n] = s * sum_k A[m][k] * W[n][k] + bias[n]
// A: [4096,1024] row-major, W: [1024,1024] row-major (both K-contiguous, "NT")
// Tiles: BM=BN=128, BK=16, 256 threads, 8x8 per-thread micro-tile.
// ---------------------------------------------------------------------------
__global__ __launch_bounds__(256) void gemm_nt_bias_kernel(
    const float* __restrict__ A, const float* __restrict__ W,
    const float* __restrict__ s_ptr, const float* __restrict__ bias,
    float* __restrict__ C)
{
    __shared__ float As[16][128];   // [k][m]
    __shared__ float Bs[16][128];   // [k][n]

    const int tid = threadIdx.x;
    const int tx  = tid & 15;       // -> n micro
    const int ty  = tid >> 4;       // -> m micro
    const int m0  = blockIdx.y * 128;
    const int n0  = blockIdx.x * 128;

    const int lr = tid >> 2;        // 0..63 tile row (and +64)
    const int lc = tid & 3;         // float4 column within 16-wide k slice

    float acc[8][8];
    #pragma unroll
    for (int i = 0; i < 8; i++)
        #pragma unroll
        for (int j = 0; j < 8; j++) acc[i][j] = 0.f;

    const float* Ap = A + (size_t)(m0 + lr) * HIDDEN + lc * 4;
    const float* Wp = W + (size_t)(n0 + lr) * HIDDEN + lc * 4;

    for (int k0 = 0; k0 < HIDDEN; k0 += 16) {
        float4 a0 = *(const float4*)(Ap);
        float4 a1 = *(const float4*)(Ap + (size_t)64 * HIDDEN);
        float4 b0 = *(const float4*)(Wp);
        float4 b1 = *(const float4*)(Wp + (size_t)64 * HIDDEN);
        Ap += 16; Wp += 16;

        __syncthreads();   // previous compute done before rewriting tiles
        As[lc*4+0][lr]    = a0.x; As[lc*4+1][lr]    = a0.y;
        As[lc*4+2][lr]    = a0.z; As[lc*4+3][lr]    = a0.w;
        As[lc*4+0][lr+64] = a1.x; As[lc*4+1][lr+64] = a1.y;
        As[lc*4+2][lr+64] = a1.z; As[lc*4+3][lr+64] = a1.w;
        Bs[lc*4+0][lr]    = b0.x; Bs[lc*4+1][lr]    = b0.y;
        Bs[lc*4+2][lr]    = b0.z; Bs[lc*4+3][lr]    = b0.w;
        Bs[lc*4+0][lr+64] = b1.x; Bs[lc*4+1][lr+64] = b1.y;
        Bs[lc*4+2][lr+64] = b1.z; Bs[lc*4+3][lr+64] = b1.w;
        __syncthreads();

        #pragma unroll
        for (int k = 0; k < 16; k++) {
            float a[8], b[8];
            *(float4*)&a[0] = *(const float4*)&As[k][ty*8];
            *(float4*)&a[4] = *(const float4*)&As[k][ty*8+4];
            *(float4*)&b[0] = *(const float4*)&Bs[k][tx*8];
            *(float4*)&b[4] = *(const float4*)&Bs[k][tx*8+4];
            #pragma unroll
            for (int i = 0; i < 8; i++)
                #pragma unroll
                for (int j = 0; j < 8; j++)
                    acc[i][j] += a[i] * b[j];
        }
    }

    const float s = *s_ptr;
    float bv[8];
    *(float4*)&bv[0] = *(const float4*)&bias[n0 + tx*8];
    *(float4*)&bv[4] = *(const float4*)&bias[n0 + tx*8 + 4];

    #pragma unroll
    for (int i = 0; i < 8; i++) {
        float* cp = C + (size_t)(m0 + ty*8 + i) * HIDDEN + n0 + tx*8;
        float4 r0, r1;
        r0.x = acc[i][0]*s + bv[0]; r0.y = acc[i][1]*s + bv[1];
        r0.z = acc[i][2]*s + bv[2]; r0.w = acc[i][3]*s + bv[3];
        r1.x = acc[i][4]*s + bv[4]; r1.y = acc[i][5]*s + bv[5];
        r1.z = acc[i][6]*s + bv[6]; r1.w = acc[i][7]*s + bv[7];
        *(float4*)cp       = r0;
        *(float4*)(cp + 4) = r1;
    }
}

// ---------------------------------------------------------------------------
// Flash attention, fp32. Q/K/V/O all [4096,1024] flat ([b,s,h*64]).
// Block: one (b, h, 64-query tile); 256 threads as 16x16; each thread owns a
// 4x4 micro-tile (4 queries x 4 keys for S, 4 queries x 4 dims for ctx).
// Smem: Qs [d][q] (pre-scaled by 1/8), KP [d][k] (reused as P^T [k][q]),
// Vs [k][d]. Exactly 48 KB.
// ---------------------------------------------------------------------------
__global__ __launch_bounds__(256) void attn_kernel(
    const float* __restrict__ Q, const float* __restrict__ K,
    const float* __restrict__ V, float* __restrict__ O)
{
    __shared__ float Qs[64][64];
    __shared__ float KP[64][64];
    __shared__ float Vs[64][64];

    const int tid = threadIdx.x;
    const int tx  = tid & 15;
    const int ty  = tid >> 4;
    const int qt  = blockIdx.x;   // 0..31
    const int h   = blockIdx.y;   // 0..15
    const int b   = blockIdx.z;   // 0..1

    const size_t head_off = (size_t)b * SEQ * HIDDEN + (size_t)h * 64;
    const float* qg = Q + head_off + (size_t)qt * 64 * HIDDEN;

    #pragma unroll
    for (int i = 0; i < 4; i++) {
        int idx = tid + i * 256;
        int r = idx >> 4, c4 = idx & 15;
        float4 t = *(const float4*)(qg + (size_t)r * HIDDEN + c4 * 4);
        Qs[c4*4+0][r] = t.x * 0.125f;
        Qs[c4*4+1][r] = t.y * 0.125f;
        Qs[c4*4+2][r] = t.z * 0.125f;
        Qs[c4*4+3][r] = t.w * 0.125f;
    }

    float m_i[4], l_i[4], acc[4][4];
    #pragma unroll
    for (int i = 0; i < 4; i++) {
        m_i[i] = -1e30f; l_i[i] = 0.f;
        #pragma unroll
        for (int j = 0; j < 4; j++) acc[i][j] = 0.f;
    }

    for (int kt = 0; kt < SEQ / 64; kt++) {
        const float* kg = K + head_off + (size_t)kt * 64 * HIDDEN;
        const float* vg = V + head_off + (size_t)kt * 64 * HIDDEN;

        __syncthreads();   // prior-tile reads (and Qs init on iter 0) complete
        #pragma unroll
        for (int i = 0; i < 4; i++) {
            int idx = tid + i * 256;
            int r = idx >> 4, c4 = idx & 15;
            float4 tk = *(const float4*)(kg + (size_t)r * HIDDEN + c4 * 4);
            KP[c4*4+0][r] = tk.x; KP[c4*4+1][r] = tk.y;
            KP[c4*4+2][r] = tk.z; KP[c4*4+3][r] = tk.w;
            float4 tv = *(const float4*)(vg + (size_t)r * HIDDEN + c4 * 4);
            *(float4*)&Vs[r][c4*4] = tv;
        }
        __syncthreads();

        // S = (Q/8) @ K^T  : 4x4 per thread
        float sc[4][4];
        #pragma unroll
        for (int i = 0; i < 4; i++)
            #pragma unroll
            for (int j = 0; j < 4; j++) sc[i][j] = 0.f;

        #pragma unroll 16
        for (int d = 0; d < 64; d++) {
            float a[4], bb[4];
            *(float4*)a  = *(const float4*)&Qs[d][ty*4];
            *(float4*)bb = *(const float4*)&KP[d][tx*4];
            #pragma unroll
            for (int i = 0; i < 4; i++)
                #pragma unroll
                for (int j = 0; j < 4; j++)
                    sc[i][j] += a[i] * bb[j];
        }

        // online softmax (row = query; reduce across tx lanes, width 16)
        #pragma unroll
        for (int i = 0; i < 4; i++) {
            float tm = fmaxf(fmaxf(sc[i][0], sc[i][1]), fmaxf(sc[i][2], sc[i][3]));
            #pragma unroll
            for (int off = 8; off >= 1; off >>= 1)
                tm = fmaxf(tm, __shfl_xor_sync(0xffffffffu, tm, off, 16));
            float mn = fmaxf(m_i[i], tm);
            float scale = expf(m_i[i] - mn);   // exp(-inf-ish)=0 on first tile
            m_i[i] = mn;
            float rs = 0.f;
            #pragma unroll
            for (int j = 0; j < 4; j++) { sc[i][j] = expf(sc[i][j] - mn); rs += sc[i][j]; }
            #pragma unroll
            for (int off = 8; off >= 1; off >>= 1)
                rs += __shfl_xor_sync(0xffffffffu, rs, off, 16);
            l_i[i] = l_i[i] * scale + rs;
            #pragma unroll
            for (int j = 0; j < 4; j++) acc[i][j] *= scale;
        }

        __syncthreads();           // everyone finished reading K from KP
        #pragma unroll
        for (int i = 0; i < 4; i++)
            #pragma unroll
            for (int j = 0; j < 4; j++)
                KP[tx*4+j][ty*4+i] = sc[i][j];   // P^T: [k][q]
        __syncthreads();

        // ctx += P @ V : 4 queries x 4 dims per thread
        #pragma unroll 16
        for (int kk = 0; kk < 64; kk++) {
            float a[4], bb[4];
            *(float4*)a  = *(const float4*)&KP[kk][ty*4];
            *(float4*)bb = *(const float4*)&Vs[kk][tx*4];
            #pragma unroll
            for (int i = 0; i < 4; i++)
                #pragma unroll
                for (int j = 0; j < 4; j++)
                    acc[i][j] += a[i] * bb[j];
        }
    }

    float* og = O + head_off + (size_t)qt * 64 * HIDDEN;
    #pragma unroll
    for (int i = 0; i < 4; i++) {
        float inv = 1.f / l_i[i];
        float4 r;
        r.x = acc[i][0] * inv; r.y = acc[i][1] * inv;
        r.z = acc[i][2] * inv; r.w = acc[i][3] * inv;
        *(float4*)(og + (size_t)(ty*4 + i) * HIDDEN + tx * 4) = r;
    }
}

// ---------------------------------------------------------------------------
// d_in order (metadata): x, w_q, s_q, b_q, w_k, s_k, b_k, w_v, s_v, b_v,
//                        w_o, s_o, b_o.   Output: [2,2048,1024] fp32.
// ---------------------------------------------------------------------------
extern "C" void kernel_launch(void* const* d_in, const int* in_sizes, int n_in,
                              void* d_out, int out_size)
{
    (void)in_sizes; (void)n_in; (void)out_size;
    const float* x   = (const float*)d_in[0];
    const float* w_q = (const float*)d_in[1];
    const float* s_q = (const float*)d_in[2];
    const float* b_q = (const float*)d_in[3];
    const float* w_k = (const float*)d_in[4];
    const float* s_k = (const float*)d_in[5];
    const float* b_k = (const float*)d_in[6];
    const float* w_v = (const float*)d_in[7];
    const float* s_v = (const float*)d_in[8];
    const float* b_v = (const float*)d_in[9];
    const float* w_o = (const float*)d_in[10];
    const float* s_o = (const float*)d_in[11];
    const float* b_o = (const float*)d_in[12];
    float* out = (float*)d_out;

    float *qp, *kp, *vp, *cp;
    cudaGetSymbolAddress((void**)&qp, g_q);
    cudaGetSymbolAddress((void**)&kp, g_k);
    cudaGetSymbolAddress((void**)&vp, g_v);
    cudaGetSymbolAddress((void**)&cp, g_ctx);

    dim3 ggrid(HIDDEN / 128, MTOT / 128);   // (8, 32)
    gemm_nt_bias_kernel<<<ggrid, 256>>>(x, w_q, s_q, b_q, qp);
    gemm_nt_bias_kernel<<<ggrid, 256>>>(x, w_k, s_k, b_k, kp);
    gemm_nt_bias_kernel<<<ggrid, 256>>>(x, w_v, s_v, b_v, vp);

    dim3 agrid(SEQ / 64, HIDDEN / 64, BATCH);   // (32, 16, 2)
    attn_kernel<<<agrid, 256>>>(qp, kp, vp, cp);

    gemm_nt_bias_kernel<<<ggrid, 256>>>(cp, w_o, s_o, b_o, out);
}

// round 2
// speedup vs baseline: 3.1514x; 3.1514x over previous
#include <cuda_runtime.h>
#include <cuda_bf16.h>
#include <cstdint>

#define HIDDEN 1024
#define SEQ    2048
#define BATCH  2
#define MTOT   4096
#define K2     2048   // hidden doubled: (hi,lo) bf16 interleaved

// ---------------- scratch (__device__ globals; no allocs allowed) ----------
__device__ __nv_bfloat16 g_x2[(size_t)MTOT * K2];
__device__ __nv_bfloat16 g_w2[4][(size_t)HIDDEN * K2];
__device__ __nv_bfloat16 g_q2[(size_t)MTOT * K2];
__device__ __nv_bfloat16 g_k2[(size_t)MTOT * K2];
__device__ __nv_bfloat16 g_v2[(size_t)MTOT * K2];
__device__ __nv_bfloat16 g_c2[(size_t)MTOT * K2];

// ---------------- helpers ---------------------------------------------------
__device__ __forceinline__ uint32_t pack_hl(float x) {
    __nv_bfloat16 hb = __float2bfloat16(x);
    float hf = __bfloat162float(hb);
    __nv_bfloat16 lb = __float2bfloat16(x - hf);
    return (uint32_t)__bfloat16_as_ushort(hb) |
           ((uint32_t)__bfloat16_as_ushort(lb) << 16);
}

__device__ __forceinline__ float ex2f(float x) {
    float y; asm("ex2.approx.f32 %0, %1;" : "=f"(y) : "f"(x)); return y;
}

__device__ __forceinline__ uint32_t smem_u32(const void* p) {
    return (uint32_t)__cvta_generic_to_shared(p);
}

__device__ __forceinline__ void ldm_x4(uint32_t* r, uint32_t addr) {
    asm volatile("ldmatrix.sync.aligned.m8n8.x4.shared.b16 {%0,%1,%2,%3}, [%4];"
        : "=r"(r[0]), "=r"(r[1]), "=r"(r[2]), "=r"(r[3]) : "r"(addr));
}
__device__ __forceinline__ void ldm_x4_t(uint32_t* r, uint32_t addr) {
    asm volatile("ldmatrix.sync.aligned.m8n8.x4.trans.shared.b16 {%0,%1,%2,%3}, [%4];"
        : "=r"(r[0]), "=r"(r[1]), "=r"(r[2]), "=r"(r[3]) : "r"(addr));
}
__device__ __forceinline__ void mma16816(float* c, const uint32_t* a,
                                         uint32_t b0, uint32_t b1) {
    asm volatile(
        "mma.sync.aligned.m16n8k16.row.col.f32.bf16.bf16.f32 "
        "{%0,%1,%2,%3}, {%4,%5,%6,%7}, {%8,%9}, {%0,%1,%2,%3};"
        : "+f"(c[0]), "+f"(c[1]), "+f"(c[2]), "+f"(c[3])
        : "r"(a[0]), "r"(a[1]), "r"(a[2]), "r"(a[3]), "r"(b0), "r"(b1));
}

// ---------------- prep kernels ---------------------------------------------
__global__ void prep_split(const float* __restrict__ in, uint32_t* __restrict__ out, int n) {
    int i = blockIdx.x * 256 + threadIdx.x;
    if (i < n) out[i] = pack_hl(in[i]);
}
__global__ void prep_dupw(const float* __restrict__ in, uint32_t* __restrict__ out, int n) {
    int i = blockIdx.x * 256 + threadIdx.x;
    if (i < n) {
        uint32_t u = __bfloat16_as_ushort(__float2bfloat16(in[i]));  // ternary: exact
        out[i] = u | (u << 16);
    }
}

// ---------------- GEMM: C[m][n] = s * sum_k' A2[m][k'] W2[n][k'] + bias[n] ---
// A2: [4096][2048] bf16 (hi/lo interleaved); W2: [1024][2048] bf16 (duplicated)
// 128x128 tile, 8 warps (4m x 2n), each warp 32m x 64n via m16n8k16.
#define GS 40   // smem k'-stride (32 + 8 pad)

template<bool SPLIT_OUT>
__global__ __launch_bounds__(256) void gemm_bf16(
    const __nv_bfloat16* __restrict__ A2, const __nv_bfloat16* __restrict__ W2,
    const float* __restrict__ s_ptr, const float* __restrict__ bias,
    void* __restrict__ outp)
{
    __shared__ __nv_bfloat16 As[128 * GS];
    __shared__ __nv_bfloat16 Bs[128 * GS];

    const int tid  = threadIdx.x;
    const int lane = tid & 31;
    const int gid  = lane >> 2, tig = lane & 3;
    const int rr   = lane & 7,  qd  = lane >> 3;
    const int arow = rr + (qd & 1) * 8, acol = (qd >> 1) * 8;  // A-type ldm offsets
    const int brow = rr + (qd >> 1) * 8, bcol = (qd & 1) * 8;  // B-type ldm offsets

    const int m0 = blockIdx.y * 128, n0 = blockIdx.x * 128;
    const int wid = tid >> 5, wm = wid >> 1, wn = wid & 1;
    const int mb = wm * 32, nb = wn * 64;

    const int lrow = tid >> 2;           // 0..63
    const int lcol = (tid & 3) * 8;      // bf16 col within 32-wide k' slice

    const __nv_bfloat16* Ag = A2 + (size_t)m0 * K2;
    const __nv_bfloat16* Wg = W2 + (size_t)n0 * K2;

    const uint32_t sA = smem_u32(As), sB = smem_u32(Bs);

    float acc[2][8][4];
    #pragma unroll
    for (int i = 0; i < 2; i++)
        #pragma unroll
        for (int j = 0; j < 8; j++)
            #pragma unroll
            for (int t = 0; t < 4; t++) acc[i][j][t] = 0.f;

    uint4 ra0, ra1, rw0, rw1;
    ra0 = *(const uint4*)(Ag + (size_t)lrow * K2 + lcol);
    ra1 = *(const uint4*)(Ag + (size_t)(lrow + 64) * K2 + lcol);
    rw0 = *(const uint4*)(Wg + (size_t)lrow * K2 + lcol);
    rw1 = *(const uint4*)(Wg + (size_t)(lrow + 64) * K2 + lcol);

    for (int it = 0; it < 64; it++) {
        __syncthreads();
        *(uint4*)&As[lrow * GS + lcol]        = ra0;
        *(uint4*)&As[(lrow + 64) * GS + lcol] = ra1;
        *(uint4*)&Bs[lrow * GS + lcol]        = rw0;
        *(uint4*)&Bs[(lrow + 64) * GS + lcol] = rw1;
        __syncthreads();

        if (it < 63) {
            int ko = (it + 1) * 32 + lcol;
            ra0 = *(const uint4*)(Ag + (size_t)lrow * K2 + ko);
            ra1 = *(const uint4*)(Ag + (size_t)(lrow + 64) * K2 + ko);
            rw0 = *(const uint4*)(Wg + (size_t)lrow * K2 + ko);
            rw1 = *(const uint4*)(Wg + (size_t)(lrow + 64) * K2 + ko);
        }

        #pragma unroll
        for (int kk = 0; kk < 32; kk += 16) {
            uint32_t a[2][4];
            #pragma unroll
            for (int i = 0; i < 2; i++)
                ldm_x4(a[i], sA + ((mb + 16 * i + arow) * GS + kk + acol) * 2);
            #pragma unroll
            for (int jj = 0; jj < 4; jj++) {
                uint32_t b[4];
                ldm_x4(b, sB + ((nb + 16 * jj + brow) * GS + kk + bcol) * 2);
                #pragma unroll
                for (int i = 0; i < 2; i++) {
                    mma16816(acc[i][2 * jj],     a[i], b[0], b[1]);
                    mma16816(acc[i][2 * jj + 1], a[i], b[2], b[3]);
                }
            }
        }
    }

    const float s = __ldg(s_ptr);
    #pragma unroll
    for (int i = 0; i < 2; i++) {
        #pragma unroll
        for (int j = 0; j < 8; j++) {
            int col  = n0 + nb + 8 * j + 2 * tig;
            float2 bv = *(const float2*)(bias + col);
            int row0 = m0 + mb + 16 * i + gid;
            float v00 = acc[i][j][0] * s + bv.x;
            float v01 = acc[i][j][1] * s + bv.y;
            float v10 = acc[i][j][2] * s + bv.x;
            float v11 = acc[i][j][3] * s + bv.y;
            if (SPLIT_OUT) {
                __nv_bfloat16* O2 = (__nv_bfloat16*)outp;
                uint2 u0 = make_uint2(pack_hl(v00), pack_hl(v01));
                uint2 u1 = make_uint2(pack_hl(v10), pack_hl(v11));
                *(uint2*)(O2 + (size_t)row0 * K2 + 2 * col)       = u0;
                *(uint2*)(O2 + (size_t)(row0 + 8) * K2 + 2 * col) = u1;
            } else {
                float* Of = (float*)outp;
                *(float2*)(Of + (size_t)row0 * HIDDEN + col)       = make_float2(v00, v01);
                *(float2*)(Of + (size_t)(row0 + 8) * HIDDEN + col) = make_float2(v10, v11);
            }
        }
    }
}

// ---------------- flash attention, bf16 MMA, hi/lo exact split ---------------
// 64-query tile per block, 4 warps (warp owns 16 query rows x 64 keys).
// smem: Qs[64][136] (reused as Ps), Ks[64][136], Vs[128][72] (hi/lo key rows).
#define SQ 136
#define SV 72
#define ATTN_SMEM ((2 * 64 * SQ + 128 * SV) * 2)

__global__ __launch_bounds__(128) void attn_bf16(
    const __nv_bfloat16* __restrict__ q2, const __nv_bfloat16* __restrict__ k2,
    const __nv_bfloat16* __restrict__ v2, __nv_bfloat16* __restrict__ c2)
{
    extern __shared__ __nv_bfloat16 sm[];
    __nv_bfloat16* Qs = sm;                 // aliased as Ps after Q frags load
    __nv_bfloat16* Ks = sm + 64 * SQ;
    __nv_bfloat16* Vs = sm + 2 * 64 * SQ;

    const int tid  = threadIdx.x;
    const int lane = tid & 31, wid = tid >> 5;
    const int gid  = lane >> 2, tig = lane & 3;
    const int rr   = lane & 7,  qd  = lane >> 3;
    const int arow = rr + (qd & 1) * 8, acol = (qd >> 1) * 8;
    const int brow = rr + (qd >> 1) * 8, bcol = (qd & 1) * 8;

    const int qt = blockIdx.x, h = blockIdx.y, bb = blockIdx.z;
    const size_t rowbase = (size_t)bb * SEQ;

    const uint32_t sQ = smem_u32(Qs), sK = smem_u32(Ks), sV = smem_u32(Vs);

    // ---- load Q' tile (64 rows x 128 bf16) ----
    #pragma unroll
    for (int i = 0; i < 8; i++) {
        int idx = tid + i * 128;
        int r = idx >> 4, g = idx & 15;
        *(uint4*)&Qs[r * SQ + g * 8] =
            *(const uint4*)(q2 + (rowbase + qt * 64 + r) * K2 + h * 128 + g * 8);
    }
    __syncthreads();

    uint32_t qf[8][4];
    #pragma unroll
    for (int s8 = 0; s8 < 8; s8++)
        ldm_x4(qf[s8], sQ + ((16 * wid + arow) * SQ + 16 * s8 + acol) * 2);

    float m_[2] = {-1e30f, -1e30f}, l_[2] = {0.f, 0.f};
    float ctx[8][4];
    #pragma unroll
    for (int j = 0; j < 8; j++)
        #pragma unroll
        for (int t = 0; t < 4; t++) ctx[j][t] = 0.f;

    for (int kt = 0; kt < SEQ / 64; kt++) {
        __syncthreads();   // prior PV reads (and Q-frag loads on kt=0) done

        // ---- fill K' and V (deinterleave hi/lo into separate rows) ----
        #pragma unroll
        for (int i = 0; i < 8; i++) {
            int idx = tid + i * 128;
            int r = idx >> 4, g = idx & 15;
            const __nv_bfloat16* kg = k2 + (rowbase + kt * 64 + r) * K2 + h * 128 + g * 8;
            *(uint4*)&Ks[r * SQ + g * 8] = *(const uint4*)kg;
            uint4 u = *(const uint4*)(v2 + (rowbase + kt * 64 + r) * K2 + h * 128 + g * 8);
            uint32_t h0 = __byte_perm(u.x, u.y, 0x5410), l0 = __byte_perm(u.x, u.y, 0x7632);
            uint32_t h1 = __byte_perm(u.z, u.w, 0x5410), l1 = __byte_perm(u.z, u.w, 0x7632);
            *(uint2*)&Vs[(2 * r) * SV + g * 4]     = make_uint2(h0, h1);
            *(uint2*)&Vs[(2 * r + 1) * SV + g * 4] = make_uint2(l0, l1);
        }
        __syncthreads();

        // ---- S = Q' K'^T ----
        float sacc[8][4];
        #pragma unroll
        for (int j = 0; j < 8; j++)
            #pragma unroll
            for (int t = 0; t < 4; t++) sacc[j][t] = 0.f;

        #pragma unroll
        for (int s8 = 0; s8 < 8; s8++) {
            #pragma unroll
            for (int jj = 0; jj < 4; jj++) {
                uint32_t b[4];
                ldm_x4(b, sK + ((16 * jj + brow) * SQ + 16 * s8 + bcol) * 2);
                mma16816(sacc[2 * jj],     qf[s8], b[0], b[1]);
                mma16816(sacc[2 * jj + 1], qf[s8], b[2], b[3]);
            }
        }

        // ---- online softmax (scaled into log2 domain) ----
        const float SC = 0.125f * 1.4426950408889634f;
        #pragma unroll
        for (int j = 0; j < 8; j++)
            #pragma unroll
            for (int t = 0; t < 4; t++) sacc[j][t] *= SC;

        #pragma unroll
        for (int r = 0; r < 2; r++) {
            float mx = -1e30f;
            #pragma unroll
            for (int j = 0; j < 8; j++)
                mx = fmaxf(mx, fmaxf(sacc[j][2 * r], sacc[j][2 * r + 1]));
            mx = fmaxf(mx, __shfl_xor_sync(0xffffffffu, mx, 1));
            mx = fmaxf(mx, __shfl_xor_sync(0xffffffffu, mx, 2));
            float mn = fmaxf(m_[r], mx);
            float corr = ex2f(m_[r] - mn);
            m_[r] = mn;
            float sum = 0.f;
            #pragma unroll
            for (int j = 0; j < 8; j++) {
                sacc[j][2 * r]     = ex2f(sacc[j][2 * r] - mn);
                sacc[j][2 * r + 1] = ex2f(sacc[j][2 * r + 1] - mn);
                sum += sacc[j][2 * r] + sacc[j][2 * r + 1];
            }
            sum += __shfl_xor_sync(0xffffffffu, sum, 1);
            sum += __shfl_xor_sync(0xffffffffu, sum, 2);
            l_[r] = l_[r] * corr + sum;
            #pragma unroll
            for (int j = 0; j < 8; j++) {
                ctx[j][2 * r]     *= corr;
                ctx[j][2 * r + 1] *= corr;
            }
        }

        // ---- store P' (hi,lo interleaved along keys) into Ps (=Qs) ----
        {
            int prow = 16 * wid + gid;
            #pragma unroll
            for (int j = 0; j < 8; j++) {
                int c = 8 * j + 2 * tig;
                *(uint2*)&Qs[prow * SQ + 2 * c] =
                    make_uint2(pack_hl(sacc[j][0]), pack_hl(sacc[j][1]));
                *(uint2*)&Qs[(prow + 8) * SQ + 2 * c] =
                    make_uint2(pack_hl(sacc[j][2]), pack_hl(sacc[j][3]));
            }
        }
        __syncthreads();

        // ---- ctx += P V  (two passes: pass2 = halfword-swapped A frags) ----
        #pragma unroll
        for (int s8 = 0; s8 < 8; s8++) {
            uint32_t a[4], aw[4];
            ldm_x4(a, sQ + ((16 * wid + arow) * SQ + 16 * s8 + acol) * 2);
            #pragma unroll
            for (int t = 0; t < 4; t++) aw[t] = __byte_perm(a[t], 0, 0x1032);
            #pragma unroll
            for (int jj = 0; jj < 4; jj++) {
                uint32_t b[4];
                ldm_x4_t(b, sV + ((16 * s8 + arow) * SV + 16 * jj + acol) * 2);
                mma16816(ctx[2 * jj],     a,  b[0], b[1]);
                mma16816(ctx[2 * jj + 1], a,  b[2], b[3]);
                mma16816(ctx[2 * jj],     aw, b[0], b[1]);
                mma16816(ctx[2 * jj + 1], aw, b[2], b[3]);
            }
        }
    }

    // ---- epilogue: normalize, split, store interleaved ctx ----
    float inv0 = 1.f / l_[0], inv1 = 1.f / l_[1];
    int r0 = qt * 64 + 16 * wid + gid;
    #pragma unroll
    for (int j = 0; j < 8; j++) {
        int d = 8 * j + 2 * tig;
        size_t col2 = 2 * (64 * h + d);
        uint2 u0 = make_uint2(pack_hl(ctx[j][0] * inv0), pack_hl(ctx[j][1] * inv0));
        uint2 u1 = make_uint2(pack_hl(ctx[j][2] * inv1), pack_hl(ctx[j][3] * inv1));
        *(uint2*)(c2 + (rowbase + r0) * K2 + col2)     = u0;
        *(uint2*)(c2 + (rowbase + r0 + 8) * K2 + col2) = u1;
    }
}

// ---------------- launch -----------------------------------------------------
extern "C" void kernel_launch(void* const* d_in, const int* in_sizes, int n_in,
                              void* d_out, int out_size)
{
    (void)in_sizes; (void)n_in; (void)out_size;
    const float* x   = (const float*)d_in[0];
    const float* w_q = (const float*)d_in[1];
    const float* s_q = (const float*)d_in[2];
    const float* b_q = (const float*)d_in[3];
    const float* w_k = (const float*)d_in[4];
    const float* s_k = (const float*)d_in[5];
    const float* b_k = (const float*)d_in[6];
    const float* w_v = (const float*)d_in[7];
    const float* s_v = (const float*)d_in[8];
    const float* b_v = (const float*)d_in[9];
    const float* w_o = (const float*)d_in[10];
    const float* s_o = (const float*)d_in[11];
    const float* b_o = (const float*)d_in[12];

    __nv_bfloat16 *x2, *w2, *q2, *k2, *v2, *c2;
    cudaGetSymbolAddress((void**)&x2, g_x2);
    cudaGetSymbolAddress((void**)&w2, g_w2);
    cudaGetSymbolAddress((void**)&q2, g_q2);
    cudaGetSymbolAddress((void**)&k2, g_k2);
    cudaGetSymbolAddress((void**)&v2, g_v2);
    cudaGetSymbolAddress((void**)&c2, g_c2);
    __nv_bfloat16* w2q = w2;
    __nv_bfloat16* w2k = w2 + (size_t)1 * HIDDEN * K2;
    __nv_bfloat16* w2v = w2 + (size_t)2 * HIDDEN * K2;
    __nv_bfloat16* w2o = w2 + (size_t)3 * HIDDEN * K2;

    cudaFuncSetAttribute(attn_bf16, cudaFuncAttributeMaxDynamicSharedMemorySize, ATTN_SMEM);

    // prep: split x to hi/lo, cast+duplicate weights
    {
        int n = MTOT * HIDDEN;
        prep_split<<<(n + 255) / 256, 256>>>(x, (uint32_t*)x2, n);
        int nw = HIDDEN * HIDDEN;
        prep_dupw<<<(nw + 255) / 256, 256>>>(w_q, (uint32_t*)w2q, nw);
        prep_dupw<<<(nw + 255) / 256, 256>>>(w_k, (uint32_t*)w2k, nw);
        prep_dupw<<<(nw + 255) / 256, 256>>>(w_v, (uint32_t*)w2v, nw);
        prep_dupw<<<(nw + 255) / 256, 256>>>(w_o, (uint32_t*)w2o, nw);
    }

    dim3 ggrid(HIDDEN / 128, MTOT / 128);  // (8, 32)
    gemm_bf16<true><<<ggrid, 256>>>(x2, w2q, s_q, b_q, q2);
    gemm_bf16<true><<<ggrid, 256>>>(x2, w2k, s_k, b_k, k2);
    gemm_bf16<true><<<ggrid, 256>>>(x2, w2v, s_v, b_v, v2);

    dim3 agrid(SEQ / 64, HIDDEN / 64, BATCH);  // (32, 16, 2)
    attn_bf16<<<agrid, 128, ATTN_SMEM>>>(q2, k2, v2, c2);

    gemm_bf16<false><<<ggrid, 256>>>(c2, w2o, s_o, b_o, d_out);
}